// round 13
// baseline (speedup 1.0000x reference)
#include <cuda_runtime.h>
#include <cuda_fp16.h>
#include <cstdint>

// ---------------- problem constants ----------------
constexpr int B  = 16384;
constexpr int F  = 24;
constexpr int P  = 276;
constexpr int MT = 128;                  // b-rows per CTA
constexpr int NTILE = B / MT;            // 128 b-tiles
constexpr int XTILE = MT * 128;          // 16 KB per (tile, field), fp16, swizzled
constexpr int WTILE = 64 * 128;          // 8 KB per pair (W^T fp16, swizzled)
constexpr unsigned XJOFF = 2u * XTILE;            // 32768 (single xj buffer)
constexpr unsigned WOFF  = XJOFF + 1u * XTILE;    // 49152 (W ring of 2)
constexpr unsigned DYN_SMEM = WOFF + 2u * WTILE;  // 65536 (64 KB -> 3 CTAs/SM)

// ---------------- device scratch (allocation-guard safe) ----------------
__device__ __half g_xs[(size_t)NTILE * F * (XTILE / 2)];  // 48 MB preswizzled x tiles
__device__ __half g_ws[(size_t)P * (WTILE / 2)];          // 2.25 MB preswizzled W^T tiles

// ---------------- helpers ----------------
__device__ __forceinline__ unsigned smem_u32(const void* p) {
    return (unsigned)__cvta_generic_to_shared(p);
}
__device__ __forceinline__ void cp16(unsigned dst, const void* src) {
    asm volatile("cp.async.cg.shared.global [%0], [%1], 16;" :: "r"(dst), "l"(src));
}
__device__ __forceinline__ void cp_commit() {
    asm volatile("cp.async.commit_group;" ::: "memory");
}
__device__ __forceinline__ void cp_wait0() {
    asm volatile("cp.async.wait_group 0;" ::: "memory");
}
__device__ __forceinline__ void ldm_x4(unsigned addr, unsigned& r0, unsigned& r1,
                                       unsigned& r2, unsigned& r3) {
    asm volatile("ldmatrix.sync.aligned.m8n8.x4.shared.b16 {%0,%1,%2,%3}, [%4];"
                 : "=r"(r0), "=r"(r1), "=r"(r2), "=r"(r3)
                 : "r"(addr));
}
__device__ __forceinline__ void mma16816(float* c, const unsigned* a,
                                         unsigned b0, unsigned b1) {
    asm volatile(
        "mma.sync.aligned.m16n8k16.row.col.f32.f16.f16.f32 "
        "{%0,%1,%2,%3}, {%4,%5,%6,%7}, {%8,%9}, {%0,%1,%2,%3};"
        : "+f"(c[0]), "+f"(c[1]), "+f"(c[2]), "+f"(c[3])
        : "r"(a[0]), "r"(a[1]), "r"(a[2]), "r"(a[3]), "r"(b0), "r"(b1));
}
__device__ __forceinline__ int pidx(int fi, int fj) {   // triu row-major pair index
    return fi * (2 * F - fi - 1) / 2 + (fj - fi - 1);
}

// ---------------- prepass: convert + pre-swizzle ----------------
__global__ void convert_x_kernel(const float* __restrict__ x) {
    int t = blockIdx.x * blockDim.x + threadIdx.x;      // chunk id < B*F*8
    int c = t & 7;
    int bf = t >> 3;
    int f = bf % F;
    int b = bf / F;
    const float4* src = reinterpret_cast<const float4*>(x + ((size_t)bf * 64 + c * 8));
    float4 v0 = src[0], v1 = src[1];
    union { uint4 u; __half2 h[4]; } pk;
    pk.h[0] = __floats2half2_rn(v0.x, v0.y);
    pk.h[1] = __floats2half2_rn(v0.z, v0.w);
    pk.h[2] = __floats2half2_rn(v1.x, v1.y);
    pk.h[3] = __floats2half2_rn(v1.z, v1.w);
    int tile = b >> 7, r = b & 127;
    size_t off = ((size_t)(tile * 24 + f) << 14) + r * 128 + ((c ^ (r & 7)) << 4);
    *reinterpret_cast<uint4*>(reinterpret_cast<char*>(g_xs) + off) = pk.u;
}
// W[p,d,e] fp32 -> preswizzled W^T tile; also zeroes out (fused)
__global__ void convert_w_kernel(const float* __restrict__ W, float* __restrict__ out) {
    int t = blockIdx.x * blockDim.x + threadIdx.x;      // < P*8*64
    if (t < B) out[t] = 0.0f;
    int e = t & 63;
    int pc = t >> 6;
    int c = pc & 7;
    int p = pc >> 3;
    const float* base = W + (size_t)p * 4096 + (size_t)c * 8 * 64 + e;
    union { uint4 u; __half h[8]; } pk;
    #pragma unroll
    for (int k = 0; k < 8; k++) pk.h[k] = __float2half_rn(base[k * 64]);
    size_t off = (size_t)p * 8192 + e * 128 + ((c ^ (e & 7)) << 4);
    *reinterpret_cast<uint4*>(reinterpret_cast<char*>(g_ws) + off) = pk.u;
}

// ---------------- main kernel ----------------
// 24 fields in 12 groups of 2. grid = (78 types, 128 b-tiles), 128 thr, 3 CTAs/SM.
//   type 0..65  : cross (g,g') -> 4 pairs (j-major: n -> j=n>>1, i=n&1)
//   type 66..77 : within g     -> 1 pair (2g, 2g+1)
// 2 xi tiles resident; xj single buffer; W ring-2; A-frags cached in registers.
__global__ __launch_bounds__(128, 3) void fmfm10_kernel(float* __restrict__ out) {
    extern __shared__ __align__(1024) char smem[];
    const int tid  = threadIdx.x;
    const int wi   = tid >> 5, lane = tid & 31;
    const int group = lane >> 2, tid4 = lane & 3;
    const int type = blockIdx.x;
    const int tile = blockIdx.y;
    const int b0   = tile * MT;

    const bool cross = (type < 66);
    int fA, fB;                 // i-side base field, j-side base field
    if (cross) {
        int g = 0, rem = type;
        while (rem >= 11 - g) { rem -= 11 - g; g++; }
        fA = 2 * g;
        fB = 2 * (g + 1 + rem);
    } else {
        fA = 2 * (type - 66);
        fB = fA + 1;            // single pair (fA, fA+1)
    }

    const unsigned sb = smem_u32(smem);
    const char* xs = reinterpret_cast<const char*>(g_xs);
    const char* ws = reinterpret_cast<const char*>(g_ws);

    // ---- preload: 2 xi tiles + W(pair 0) + xj(j=0) for cross ----
    #pragma unroll
    for (int s = 0; s < 2; s++) {
        const char* g = xs + ((size_t)(tile * 24 + fA + s) << 14);
        #pragma unroll
        for (int c = tid; c < 1024; c += 128)
            cp16(sb + s * XTILE + c * 16, g + c * 16);
    }
    {
        const char* g = ws + (size_t)pidx(fA, fB) * WTILE;
        #pragma unroll
        for (int c = tid; c < 512; c += 128)
            cp16(sb + WOFF + c * 16, g + c * 16);
    }
    if (cross) {
        const char* gx = xs + ((size_t)(tile * 24 + fB) << 14);
        #pragma unroll
        for (int c = tid; c < 1024; c += 128)
            cp16(sb + XJOFF + c * 16, gx + c * 16);
    }
    cp_commit();

    unsigned Af[2][2][4][4];   // A-fragment cache: [i-slot][mt][ks][reg]
    float acc[2][8][4];
    float tot[2][2] = {{0.f, 0.f}, {0.f, 0.f}};

    // ldsm offsets (ptxas hoists fine; keep code simple)
    const int hi = lane >> 4;

    #define FILL_A(s)                                                          \
        _Pragma("unroll")                                                      \
        for (int mt = 0; mt < 2; mt++) {                                       \
            const int r = wi * 32 + mt * 16 + (lane & 15);                     \
            _Pragma("unroll")                                                  \
            for (int ks = 0; ks < 4; ks++) {                                   \
                const int ch = ks * 2 + hi;                                    \
                ldm_x4(sb + (unsigned)(s) * XTILE +                            \
                       (unsigned)(r * 128 + ((ch ^ (r & 7)) << 4)),            \
                       Af[s][mt][ks][0], Af[s][mt][ks][1],                     \
                       Af[s][mt][ks][2], Af[s][mt][ks][3]);                    \
            }                                                                  \
        }

    #define ZERO_ACC()                                                        \
        _Pragma("unroll")                                                     \
        for (int a = 0; a < 2; a++)                                           \
            _Pragma("unroll")                                                 \
            for (int b = 0; b < 8; b++)                                       \
                _Pragma("unroll")                                             \
                for (int c = 0; c < 4; c++) acc[a][b][c] = 0.0f;

    #define MMA_PAIR(ii, w_base)                                               \
        _Pragma("unroll")                                                      \
        for (int ks = 0; ks < 4; ks++) {                                       \
            _Pragma("unroll")                                                  \
            for (int h = 0; h < 4; h++) {                                      \
                const int r = h * 16 + (lane & 15);                            \
                const int ch = ks * 2 + hi;                                    \
                unsigned br0, br1, br2, br3;                                   \
                ldm_x4((w_base) +                                              \
                       (unsigned)(r * 128 + ((ch ^ (r & 7)) << 4)),            \
                       br0, br1, br2, br3);                                    \
                mma16816(acc[0][h * 2],     Af[ii][0][ks], br0, br2);          \
                mma16816(acc[0][h * 2 + 1], Af[ii][0][ks], br1, br3);          \
                mma16816(acc[1][h * 2],     Af[ii][1][ks], br0, br2);          \
                mma16816(acc[1][h * 2 + 1], Af[ii][1][ks], br1, br3);          \
            }                                                                  \
        }

    #define EPILOGUE(xjp)                                                      \
        _Pragma("unroll")                                                      \
        for (int mt = 0; mt < 2; mt++) {                                       \
            const int r0 = wi * 32 + mt * 16 + group;                          \
            float s0 = 0.0f, s1 = 0.0f;                                        \
            _Pragma("unroll")                                                  \
            for (int nt = 0; nt < 8; nt++) {                                   \
                const unsigned off =                                           \
                    (unsigned)(r0 * 128 + ((nt ^ (r0 & 7)) << 4) + tid4 * 4);  \
                const __half2 x0 = *reinterpret_cast<const __half2*>((xjp) + off);          \
                const __half2 x1 = *reinterpret_cast<const __half2*>((xjp) + off + 1024);   \
                float2 f0 = __half22float2(x0);                                \
                float2 f1 = __half22float2(x1);                                \
                s0 = fmaf(acc[mt][nt][0], f0.x, s0);                           \
                s0 = fmaf(acc[mt][nt][1], f0.y, s0);                           \
                s1 = fmaf(acc[mt][nt][2], f1.x, s1);                           \
                s1 = fmaf(acc[mt][nt][3], f1.y, s1);                           \
            }                                                                  \
            tot[mt][0] += s0;                                                  \
            tot[mt][1] += s1;                                                  \
        }

    if (!cross) {
        // ---- single within-group pair (fA, fA+1): xj = xi slot 1 ----
        cp_wait0();
        __syncthreads();
        FILL_A(0)
        ZERO_ACC()
        MMA_PAIR(0, sb + WOFF)
        EPILOGUE(smem + XTILE)
    } else {
        for (int n = 0; n < 4; n++) {
            const int j = n >> 1, i = n & 1;

            cp_wait0();
            __syncthreads();             // publish group issued last iter

            if (n == 0) { FILL_A(0) FILL_A(1) }

            // prefetch pair n+1's W (ring-2) and xj(1) at n==2
            {
                const int m = n + 1;
                if (m < 4) {
                    const int j2 = m >> 1, i2 = m & 1;
                    const char* g = ws + (size_t)pidx(fA + i2, fB + j2) * WTILE;
                    const unsigned wdst = sb + WOFF + ((unsigned)(m & 1)) * WTILE;
                    #pragma unroll
                    for (int c = tid; c < 512; c += 128)
                        cp16(wdst + c * 16, g + c * 16);
                }
                if (n == 2) {            // xj(1): last reader (epilogue j=0) pre-dates this barrier
                    const char* gx = xs + ((size_t)(tile * 24 + fB + 1) << 14);
                    #pragma unroll
                    for (int c = tid; c < 1024; c += 128)
                        cp16(sb + XJOFF + c * 16, gx + c * 16);
                }
                cp_commit();
            }

            if (i == 0) { ZERO_ACC() }

            const unsigned w_base = sb + WOFF + ((unsigned)(n & 1)) * WTILE;
            if (i == 0) { MMA_PAIR(0, w_base) }
            else        { MMA_PAIR(1, w_base) }

            if (i == 1) { EPILOGUE(smem + XJOFF) }
        }
    }
    #undef FILL_A
    #undef ZERO_ACC
    #undef MMA_PAIR
    #undef EPILOGUE

    // ---- final reduction + writeback (one atomicAdd per row) ----
    #pragma unroll
    for (int mt = 0; mt < 2; mt++)
        #pragma unroll
        for (int h = 0; h < 2; h++) {
            float v = tot[mt][h];
            v += __shfl_xor_sync(0xffffffffu, v, 1);
            v += __shfl_xor_sync(0xffffffffu, v, 2);
            if (tid4 == 0)
                atomicAdd(out + b0 + wi * 32 + mt * 16 + group + h * 8, v);
        }
}

// ---------------- launch ----------------
extern "C" void kernel_launch(void* const* d_in, const int* in_sizes, int n_in,
                              void* d_out, int out_size) {
    const float* x = (const float*)d_in[0];
    const float* W = (const float*)d_in[1];
    float* out = (float*)d_out;

    static bool attr_done = false;
    if (!attr_done) {
        cudaFuncSetAttribute(fmfm10_kernel, cudaFuncAttributeMaxDynamicSharedMemorySize, DYN_SMEM);
        attr_done = true;
    }

    convert_x_kernel<<<(B * F * 8) / 256, 256>>>(x);
    convert_w_kernel<<<(P * 8 * 64) / 256, 256>>>(W, out);   // also zeroes out

    dim3 grid(78, NTILE);   // 66 cross types first, 12 tiny within types as tail fillers
    fmfm10_kernel<<<grid, 128, DYN_SMEM>>>(out);
}

// round 15
// speedup vs baseline: 1.1145x; 1.1145x over previous
#include <cuda_runtime.h>
#include <cuda_fp16.h>
#include <cstdint>

// ---------------- problem constants ----------------
constexpr int B  = 16384;
constexpr int F  = 24;
constexpr int P  = 276;
constexpr int MT = 128;                  // b-rows per CTA
constexpr int NTILE = B / MT;            // 128 b-tiles
constexpr int XTILE = MT * 128;          // 16 KB per (tile, field), fp16, swizzled
constexpr int WTILE = 64 * 128;          // 8 KB per pair (W^T fp16, swizzled)
constexpr unsigned XJOFF = 4u * XTILE;            //  65536 (single xj buffer)
constexpr unsigned WOFF  = XJOFF + 1u * XTILE;    //  81920 (W ring of 4)
constexpr unsigned DYN_SMEM = WOFF + 4u * WTILE;  // 114688 (112 KB -> 2 CTAs/SM)

// ---------------- device scratch (allocation-guard safe) ----------------
__device__ __half g_xs[(size_t)NTILE * F * (XTILE / 2)];  // 48 MB preswizzled x tiles
__device__ __half g_ws[(size_t)P * (WTILE / 2)];          // 2.25 MB preswizzled W^T tiles

// ---------------- helpers ----------------
__device__ __forceinline__ unsigned smem_u32(const void* p) {
    return (unsigned)__cvta_generic_to_shared(p);
}
__device__ __forceinline__ void cp16(unsigned dst, const void* src) {
    asm volatile("cp.async.cg.shared.global [%0], [%1], 16;" :: "r"(dst), "l"(src));
}
__device__ __forceinline__ void cp_commit() {
    asm volatile("cp.async.commit_group;" ::: "memory");
}
__device__ __forceinline__ void cp_wait0() {
    asm volatile("cp.async.wait_group 0;" ::: "memory");
}
__device__ __forceinline__ void ldm_x4(unsigned addr, unsigned& r0, unsigned& r1,
                                       unsigned& r2, unsigned& r3) {
    asm volatile("ldmatrix.sync.aligned.m8n8.x4.shared.b16 {%0,%1,%2,%3}, [%4];"
                 : "=r"(r0), "=r"(r1), "=r"(r2), "=r"(r3)
                 : "r"(addr));
}
__device__ __forceinline__ void mma16816(float* c, const unsigned* a,
                                         unsigned b0, unsigned b1) {
    asm volatile(
        "mma.sync.aligned.m16n8k16.row.col.f32.f16.f16.f32 "
        "{%0,%1,%2,%3}, {%4,%5,%6,%7}, {%8,%9}, {%0,%1,%2,%3};"
        : "+f"(c[0]), "+f"(c[1]), "+f"(c[2]), "+f"(c[3])
        : "r"(a[0]), "r"(a[1]), "r"(a[2]), "r"(a[3]), "r"(b0), "r"(b1));
}
__device__ __forceinline__ int pidx(int fi, int fj) {   // triu row-major pair index
    return fi * (2 * F - fi - 1) / 2 + (fj - fi - 1);
}

// ---------------- fused prepass: convert x + convert W + zero out ----------------
// grid = 12288 x 256. Every thread converts one 16B x-chunk; the first 552
// blocks additionally convert one W chunk; the first 64 blocks zero out.
__global__ void prepass_kernel(const float* __restrict__ x,
                               const float* __restrict__ W,
                               float* __restrict__ out) {
    const int t = blockIdx.x * blockDim.x + threadIdx.x;

    // ---- zero out (first 64 blocks) ----
    if (t < B) out[t] = 0.0f;

    // ---- x convert + pre-swizzle (all blocks): chunk id t < B*F*8 ----
    {
        int c = t & 7;
        int bf = t >> 3;
        int f = bf % F;
        int b = bf / F;
        const float4* src = reinterpret_cast<const float4*>(x + ((size_t)bf * 64 + c * 8));
        float4 v0 = src[0], v1 = src[1];
        union { uint4 u; __half2 h[4]; } pk;
        pk.h[0] = __floats2half2_rn(v0.x, v0.y);
        pk.h[1] = __floats2half2_rn(v0.z, v0.w);
        pk.h[2] = __floats2half2_rn(v1.x, v1.y);
        pk.h[3] = __floats2half2_rn(v1.z, v1.w);
        int tile = b >> 7, r = b & 127;
        size_t off = ((size_t)(tile * 24 + f) << 14) + r * 128 + ((c ^ (r & 7)) << 4);
        *reinterpret_cast<uint4*>(reinterpret_cast<char*>(g_xs) + off) = pk.u;
    }

    // ---- W convert + pre-swizzle (first 552 blocks): chunk id t < P*8*64 ----
    if (t < P * 8 * 64) {
        int e = t & 63;
        int pc = t >> 6;
        int c = pc & 7;
        int p = pc >> 3;
        const float* base = W + (size_t)p * 4096 + (size_t)c * 8 * 64 + e;
        union { uint4 u; __half h[8]; } pk;
        #pragma unroll
        for (int k = 0; k < 8; k++) pk.h[k] = __float2half_rn(base[k * 64]);
        size_t off = (size_t)p * 8192 + e * 128 + ((c ^ (e & 7)) << 4);
        *reinterpret_cast<uint4*>(reinterpret_cast<char*>(g_ws) + off) = pk.u;
    }
}

// ---------------- main kernel (R9 structure — measured best) ----------------
// 24 fields in 6 groups of 4. grid = (21 types, 128 b-tiles), 128 thr, 2 CTAs/SM.
// 4 warps (rg=4, cg=1). A-fragments for all 4 xi tiles cached in registers.
// Pairs processed in BLOCKS OF 2: one cp.async group + one barrier per block.
// W ring-4; xj single-buffered (issued at j's first block, consumed one block later).
__global__ __launch_bounds__(128, 2) void fmfm9_kernel(float* __restrict__ out) {
    extern __shared__ __align__(1024) char smem[];
    const int tid  = threadIdx.x;
    const int wi   = tid >> 5, lane = tid & 31;
    const int group = lane >> 2, tid4 = lane & 3;
    const int type = blockIdx.x;
    const int tile = blockIdx.y;
    const int b0   = tile * MT;

    const bool cross = (type >= 6);
    int fi0, fj0, npairs;
    if (!cross) { fi0 = type * 4; fj0 = fi0; npairs = 6; }
    else {
        const int c = type - 6;
        const int ga[15] = {0,0,0,0,0,1,1,1,1,2,2,2,3,3,4};
        const int gb[15] = {1,2,3,4,5,2,3,4,5,3,4,5,4,5,5};
        fi0 = ga[c] * 4; fj0 = gb[c] * 4; npairs = 16;
    }
    // within-type pair decode tables (j-major)
    const int wj[6] = {1,2,2,3,3,3};
    const int wiid[6] = {0,0,1,0,1,2};

    const unsigned sb = smem_u32(smem);
    const char* xs = reinterpret_cast<const char*>(g_xs);
    const char* ws = reinterpret_cast<const char*>(g_ws);

    // hoisted ldsm offsets
    unsigned offA[2][4], offB[4][4];
    {
        const int hi = lane >> 4;
        #pragma unroll
        for (int mt = 0; mt < 2; mt++) {
            const int r = wi * 32 + mt * 16 + (lane & 15);
            #pragma unroll
            for (int ks = 0; ks < 4; ks++) {
                const int ch = ks * 2 + hi;
                offA[mt][ks] = (unsigned)(r * 128 + ((ch ^ (r & 7)) << 4));
            }
        }
        #pragma unroll
        for (int h = 0; h < 4; h++) {
            const int r = h * 16 + (lane & 15);
            #pragma unroll
            for (int ks = 0; ks < 4; ks++) {
                const int ch = ks * 2 + hi;
                offB[h][ks] = (unsigned)(r * 128 + ((ch ^ (r & 7)) << 4));
            }
        }
    }

    // ---- preload: 4 xi tiles + W(0,1) + xj(j=0) for cross ----
    #pragma unroll
    for (int s = 0; s < 4; s++) {
        const char* g = xs + ((size_t)(tile * 24 + fi0 + s) << 14);
        #pragma unroll
        for (int c = tid; c < 1024; c += 128)
            cp16(sb + s * XTILE + c * 16, g + c * 16);
    }
    #pragma unroll
    for (int m = 0; m < 2; m++) {
        int pfj = cross ? fj0 : fi0 + wj[m];
        int pfi = cross ? fi0 + m : fi0 + wiid[m];
        const char* g = ws + (size_t)pidx(pfi, pfj) * WTILE;
        #pragma unroll
        for (int c = tid; c < 512; c += 128)
            cp16(sb + WOFF + (unsigned)m * WTILE + c * 16, g + c * 16);
    }
    if (cross) {
        const char* gx = xs + ((size_t)(tile * 24 + fj0) << 14);
        #pragma unroll
        for (int c = tid; c < 1024; c += 128)
            cp16(sb + XJOFF + c * 16, gx + c * 16);
    }
    cp_commit();

    unsigned Af[4][2][4][4];   // A-fragment cache: [i-tile][mt][ks][reg]
    float acc[2][8][4];
    float tot[2][2] = {{0.f, 0.f}, {0.f, 0.f}};

    for (int n = 0; n < npairs; n += 2) {
        cp_wait0();
        __syncthreads();                 // publish group issued last block

        // ---- one-time A-fragment register fill ----
        if (n == 0) {
            #pragma unroll
            for (int s = 0; s < 4; s++) {
                const unsigned xb = sb + (unsigned)s * XTILE;
                #pragma unroll
                for (int mt = 0; mt < 2; mt++)
                    #pragma unroll
                    for (int ks = 0; ks < 4; ks++)
                        ldm_x4(xb + offA[mt][ks],
                               Af[s][mt][ks][0], Af[s][mt][ks][1],
                               Af[s][mt][ks][2], Af[s][mt][ks][3]);
            }
        }

        // ---- prefetch block n+2: W(n+2), W(n+3) [+ xj(j) at j's first block] ----
        {
            if (n + 2 < npairs) {
                #pragma unroll
                for (int q = 0; q < 2; q++) {
                    int m = n + 2 + q;
                    int j2 = cross ? (m >> 2) : wj[m % 6];
                    int i2 = cross ? (m & 3)  : wiid[m % 6];
                    int pfi = fi0 + i2;
                    int pfj = cross ? fj0 + j2 : fi0 + j2;
                    const char* g = ws + (size_t)pidx(pfi, pfj) * WTILE;
                    unsigned wdst = sb + WOFF + ((unsigned)(m & 3)) * WTILE;
                    #pragma unroll
                    for (int c = tid; c < 512; c += 128)
                        cp16(wdst + c * 16, g + c * 16);
                }
            }
            if (cross && n > 0 && (n & 3) == 0) {   // first block of j = n/4
                const char* gx = xs + ((size_t)(tile * 24 + fj0 + (n >> 2)) << 14);
                #pragma unroll
                for (int c = tid; c < 1024; c += 128)
                    cp16(sb + XJOFF + c * 16, gx + c * 16);
            }
            cp_commit();                 // empty group on tail keeps accounting uniform
        }

        // ---- two pairs ----
        #pragma unroll
        for (int q = 0; q < 2; q++) {
            const int m = n + q;
            const int j = cross ? (m >> 2) : wj[m % 6];
            const int i = cross ? (m & 3)  : wiid[m % 6];
            const bool jlast = cross ? (i == 3) : (i == j - 1);

            if (i == 0) {
                #pragma unroll
                for (int a = 0; a < 2; a++)
                    #pragma unroll
                    for (int b = 0; b < 8; b++)
                        #pragma unroll
                        for (int c = 0; c < 4; c++) acc[a][b][c] = 0.0f;
            }

            const unsigned w_base = sb + WOFF + ((unsigned)(m & 3)) * WTILE;

            #define MMA_PAIR(ii)                                                   \
                _Pragma("unroll")                                                  \
                for (int ks = 0; ks < 4; ks++) {                                   \
                    _Pragma("unroll")                                              \
                    for (int h = 0; h < 4; h++) {                                  \
                        unsigned br0, br1, br2, br3;                               \
                        ldm_x4(w_base + offB[h][ks], br0, br1, br2, br3);          \
                        mma16816(acc[0][h * 2],     Af[ii][0][ks], br0, br2);      \
                        mma16816(acc[0][h * 2 + 1], Af[ii][0][ks], br1, br3);      \
                        mma16816(acc[1][h * 2],     Af[ii][1][ks], br0, br2);      \
                        mma16816(acc[1][h * 2 + 1], Af[ii][1][ks], br1, br3);      \
                    }                                                              \
                }

            if      (i == 0) { MMA_PAIR(0) }
            else if (i == 1) { MMA_PAIR(1) }
            else if (i == 2) { MMA_PAIR(2) }
            else             { MMA_PAIR(3) }
            #undef MMA_PAIR

            // ---- epilogue at end of j: dot rows of acc with x_j ----
            if (jlast) {
                const char* xjp = cross ? (smem + XJOFF)
                                        : (smem + (size_t)j * XTILE);
                #pragma unroll
                for (int mt = 0; mt < 2; mt++) {
                    const int r0 = wi * 32 + mt * 16 + group;
                    float s0 = 0.0f, s1 = 0.0f;
                    #pragma unroll
                    for (int nt = 0; nt < 8; nt++) {
                        const unsigned off =
                            (unsigned)(r0 * 128 + ((nt ^ (r0 & 7)) << 4) + tid4 * 4);
                        // row r0+8 shares the swizzle term ((r0+8)&7 == r0&7)
                        const __half2 x0 = *reinterpret_cast<const __half2*>(xjp + off);
                        const __half2 x1 = *reinterpret_cast<const __half2*>(xjp + off + 1024);
                        float2 f0 = __half22float2(x0);
                        float2 f1 = __half22float2(x1);
                        s0 = fmaf(acc[mt][nt][0], f0.x, s0);
                        s0 = fmaf(acc[mt][nt][1], f0.y, s0);
                        s1 = fmaf(acc[mt][nt][2], f1.x, s1);
                        s1 = fmaf(acc[mt][nt][3], f1.y, s1);
                    }
                    tot[mt][0] += s0;
                    tot[mt][1] += s1;
                }
            }
        }
    }

    // ---- final reduction + writeback (one atomicAdd per row) ----
    #pragma unroll
    for (int mt = 0; mt < 2; mt++)
        #pragma unroll
        for (int h = 0; h < 2; h++) {
            float v = tot[mt][h];
            v += __shfl_xor_sync(0xffffffffu, v, 1);
            v += __shfl_xor_sync(0xffffffffu, v, 2);
            if (tid4 == 0)
                atomicAdd(out + b0 + wi * 32 + mt * 16 + group + h * 8, v);
        }
}

// ---------------- launch ----------------
extern "C" void kernel_launch(void* const* d_in, const int* in_sizes, int n_in,
                              void* d_out, int out_size) {
    const float* x = (const float*)d_in[0];
    const float* W = (const float*)d_in[1];
    float* out = (float*)d_out;

    static bool attr_done = false;
    if (!attr_done) {
        cudaFuncSetAttribute(fmfm9_kernel, cudaFuncAttributeMaxDynamicSharedMemorySize, DYN_SMEM);
        attr_done = true;
    }

    // single fused prepass: x convert + W convert + zero out
    prepass_kernel<<<(B * F * 8) / 256, 256>>>(x, W, out);

    dim3 grid(21, NTILE);   // type fast dim -> mixed CTA lengths per wave
    fmfm9_kernel<<<grid, 128, DYN_SMEM>>>(out);
}

// round 17
// speedup vs baseline: 1.1380x; 1.0211x over previous
#include <cuda_runtime.h>
#include <cuda_fp16.h>
#include <cstdint>

// ---------------- problem constants ----------------
constexpr int B  = 16384;
constexpr int F  = 24;
constexpr int P  = 276;
constexpr int MT = 128;                  // b-rows per CTA
constexpr int NTILE = B / MT;            // 128 b-tiles
constexpr int XTILE = MT * 128;          // 16 KB per (tile, field), fp16, swizzled
constexpr int WTILE = 64 * 128;          // 8 KB per pair (W^T fp16, swizzled)
constexpr unsigned XJOFF = 4u * XTILE;            //  65536 (single xj buffer)
constexpr unsigned WOFF  = XJOFF + 1u * XTILE;    //  81920 (W ring of 4)
constexpr unsigned DYN_SMEM = WOFF + 4u * WTILE;  // 114688 (112 KB -> 2 CTAs/SM)

// ---------------- device scratch (allocation-guard safe) ----------------
__device__ __half g_xs[(size_t)NTILE * F * (XTILE / 2)];  // 48 MB preswizzled x tiles
__device__ __half g_ws[(size_t)P * (WTILE / 2)];          // 2.25 MB preswizzled W^T tiles

// ---------------- helpers ----------------
__device__ __forceinline__ unsigned smem_u32(const void* p) {
    return (unsigned)__cvta_generic_to_shared(p);
}
__device__ __forceinline__ void cp16(unsigned dst, const void* src) {
    asm volatile("cp.async.cg.shared.global [%0], [%1], 16;" :: "r"(dst), "l"(src));
}
__device__ __forceinline__ void cp_commit() {
    asm volatile("cp.async.commit_group;" ::: "memory");
}
__device__ __forceinline__ void cp_wait0() {
    asm volatile("cp.async.wait_group 0;" ::: "memory");
}
__device__ __forceinline__ void ldm_x4(unsigned addr, unsigned& r0, unsigned& r1,
                                       unsigned& r2, unsigned& r3) {
    asm volatile("ldmatrix.sync.aligned.m8n8.x4.shared.b16 {%0,%1,%2,%3}, [%4];"
                 : "=r"(r0), "=r"(r1), "=r"(r2), "=r"(r3)
                 : "r"(addr));
}
__device__ __forceinline__ void mma16816(float* c, const unsigned* a,
                                         unsigned b0, unsigned b1) {
    asm volatile(
        "mma.sync.aligned.m16n8k16.row.col.f32.f16.f16.f32 "
        "{%0,%1,%2,%3}, {%4,%5,%6,%7}, {%8,%9}, {%0,%1,%2,%3};"
        : "+f"(c[0]), "+f"(c[1]), "+f"(c[2]), "+f"(c[3])
        : "r"(a[0]), "r"(a[1]), "r"(a[2]), "r"(a[3]), "r"(b0), "r"(b1));
}
__device__ __forceinline__ int pidx(int fi, int fj) {   // triu row-major pair index
    return fi * (2 * F - fi - 1) / 2 + (fj - fi - 1);
}

// ---------------- fused prepass: convert x + convert W + zero out ----------------
__global__ void prepass_kernel(const float* __restrict__ x,
                               const float* __restrict__ W,
                               float* __restrict__ out) {
    const int t = blockIdx.x * blockDim.x + threadIdx.x;

    // ---- zero out (first 64 blocks) ----
    if (t < B) out[t] = 0.0f;

    // ---- x convert + pre-swizzle (all blocks): chunk id t < B*F*8 ----
    {
        int c = t & 7;
        int bf = t >> 3;
        int f = bf % F;
        int b = bf / F;
        const float4* src = reinterpret_cast<const float4*>(x + ((size_t)bf * 64 + c * 8));
        float4 v0 = src[0], v1 = src[1];
        union { uint4 u; __half2 h[4]; } pk;
        pk.h[0] = __floats2half2_rn(v0.x, v0.y);
        pk.h[1] = __floats2half2_rn(v0.z, v0.w);
        pk.h[2] = __floats2half2_rn(v1.x, v1.y);
        pk.h[3] = __floats2half2_rn(v1.z, v1.w);
        int tile = b >> 7, r = b & 127;
        size_t off = ((size_t)(tile * 24 + f) << 14) + r * 128 + ((c ^ (r & 7)) << 4);
        *reinterpret_cast<uint4*>(reinterpret_cast<char*>(g_xs) + off) = pk.u;
    }

    // ---- W convert + pre-swizzle (first 552 blocks): chunk id t < P*8*64 ----
    if (t < P * 8 * 64) {
        int e = t & 63;
        int pc = t >> 6;
        int c = pc & 7;
        int p = pc >> 3;
        const float* base = W + (size_t)p * 4096 + (size_t)c * 8 * 64 + e;
        union { uint4 u; __half h[8]; } pk;
        #pragma unroll
        for (int k = 0; k < 8; k++) pk.h[k] = __float2half_rn(base[k * 64]);
        size_t off = (size_t)p * 8192 + e * 128 + ((c ^ (e & 7)) << 4);
        *reinterpret_cast<uint4*>(reinterpret_cast<char*>(g_ws) + off) = pk.u;
    }
}

// ---------------- main kernel (R9 structure + pipelined B-ldsm) ----------------
// 24 fields in 6 groups of 4. grid = (21 types, 128 b-tiles), 128 thr, 2 CTAs/SM.
// 4 warps (rg=4, cg=1). A-fragments for all 4 xi tiles cached in registers.
// Pairs processed in BLOCKS OF 2: one cp.async group + one barrier per block.
// W ring-4; xj single-buffered. B-fragments double-buffered in registers so each
// ldsm is issued 8 MMAs ahead of its first consumer.
__global__ __launch_bounds__(128, 2) void fmfm11_kernel(float* __restrict__ out) {
    extern __shared__ __align__(1024) char smem[];
    const int tid  = threadIdx.x;
    const int wi   = tid >> 5, lane = tid & 31;
    const int group = lane >> 2, tid4 = lane & 3;
    const int type = blockIdx.x;
    const int tile = blockIdx.y;
    const int b0   = tile * MT;

    const bool cross = (type >= 6);
    int fi0, fj0, npairs;
    if (!cross) { fi0 = type * 4; fj0 = fi0; npairs = 6; }
    else {
        const int c = type - 6;
        const int ga[15] = {0,0,0,0,0,1,1,1,1,2,2,2,3,3,4};
        const int gb[15] = {1,2,3,4,5,2,3,4,5,3,4,5,4,5,5};
        fi0 = ga[c] * 4; fj0 = gb[c] * 4; npairs = 16;
    }
    // within-type pair decode tables (j-major)
    const int wj[6] = {1,2,2,3,3,3};
    const int wiid[6] = {0,0,1,0,1,2};

    const unsigned sb = smem_u32(smem);
    const char* xs = reinterpret_cast<const char*>(g_xs);
    const char* ws = reinterpret_cast<const char*>(g_ws);

    // hoisted ldsm offsets
    unsigned offA[2][4], offB[4][4];
    {
        const int hi = lane >> 4;
        #pragma unroll
        for (int mt = 0; mt < 2; mt++) {
            const int r = wi * 32 + mt * 16 + (lane & 15);
            #pragma unroll
            for (int ks = 0; ks < 4; ks++) {
                const int ch = ks * 2 + hi;
                offA[mt][ks] = (unsigned)(r * 128 + ((ch ^ (r & 7)) << 4));
            }
        }
        #pragma unroll
        for (int h = 0; h < 4; h++) {
            const int r = h * 16 + (lane & 15);
            #pragma unroll
            for (int ks = 0; ks < 4; ks++) {
                const int ch = ks * 2 + hi;
                offB[h][ks] = (unsigned)(r * 128 + ((ch ^ (r & 7)) << 4));
            }
        }
    }

    // ---- preload: 4 xi tiles + W(0,1) + xj(j=0) for cross ----
    #pragma unroll
    for (int s = 0; s < 4; s++) {
        const char* g = xs + ((size_t)(tile * 24 + fi0 + s) << 14);
        #pragma unroll
        for (int c = tid; c < 1024; c += 128)
            cp16(sb + s * XTILE + c * 16, g + c * 16);
    }
    #pragma unroll
    for (int m = 0; m < 2; m++) {
        int pfj = cross ? fj0 : fi0 + wj[m];
        int pfi = cross ? fi0 + m : fi0 + wiid[m];
        const char* g = ws + (size_t)pidx(pfi, pfj) * WTILE;
        #pragma unroll
        for (int c = tid; c < 512; c += 128)
            cp16(sb + WOFF + (unsigned)m * WTILE + c * 16, g + c * 16);
    }
    if (cross) {
        const char* gx = xs + ((size_t)(tile * 24 + fj0) << 14);
        #pragma unroll
        for (int c = tid; c < 1024; c += 128)
            cp16(sb + XJOFF + c * 16, gx + c * 16);
    }
    cp_commit();

    unsigned Af[4][2][4][4];   // A-fragment cache: [i-tile][mt][ks][reg]
    float acc[2][8][4];
    float tot[2][2] = {{0.f, 0.f}, {0.f, 0.f}};

    for (int n = 0; n < npairs; n += 2) {
        cp_wait0();
        __syncthreads();                 // publish group issued last block

        // ---- one-time A-fragment register fill ----
        if (n == 0) {
            #pragma unroll
            for (int s = 0; s < 4; s++) {
                const unsigned xb = sb + (unsigned)s * XTILE;
                #pragma unroll
                for (int mt = 0; mt < 2; mt++)
                    #pragma unroll
                    for (int ks = 0; ks < 4; ks++)
                        ldm_x4(xb + offA[mt][ks],
                               Af[s][mt][ks][0], Af[s][mt][ks][1],
                               Af[s][mt][ks][2], Af[s][mt][ks][3]);
            }
        }

        // ---- prefetch block n+2: W(n+2), W(n+3) [+ xj(j) at j's first block] ----
        {
            if (n + 2 < npairs) {
                #pragma unroll
                for (int q = 0; q < 2; q++) {
                    int m = n + 2 + q;
                    int j2 = cross ? (m >> 2) : wj[m % 6];
                    int i2 = cross ? (m & 3)  : wiid[m % 6];
                    int pfi = fi0 + i2;
                    int pfj = cross ? fj0 + j2 : fi0 + j2;
                    const char* g = ws + (size_t)pidx(pfi, pfj) * WTILE;
                    unsigned wdst = sb + WOFF + ((unsigned)(m & 3)) * WTILE;
                    #pragma unroll
                    for (int c = tid; c < 512; c += 128)
                        cp16(wdst + c * 16, g + c * 16);
                }
            }
            if (cross && n > 0 && (n & 3) == 0) {   // first block of j = n/4
                const char* gx = xs + ((size_t)(tile * 24 + fj0 + (n >> 2)) << 14);
                #pragma unroll
                for (int c = tid; c < 1024; c += 128)
                    cp16(sb + XJOFF + c * 16, gx + c * 16);
            }
            cp_commit();                 // empty group on tail keeps accounting uniform
        }

        // ---- two pairs ----
        #pragma unroll
        for (int q = 0; q < 2; q++) {
            const int m = n + q;
            const int j = cross ? (m >> 2) : wj[m % 6];
            const int i = cross ? (m & 3)  : wiid[m % 6];
            const bool jlast = cross ? (i == 3) : (i == j - 1);

            if (i == 0) {
                #pragma unroll
                for (int a = 0; a < 2; a++)
                    #pragma unroll
                    for (int b = 0; b < 8; b++)
                        #pragma unroll
                        for (int c = 0; c < 4; c++) acc[a][b][c] = 0.0f;
            }

            const unsigned w_base = sb + WOFF + ((unsigned)(m & 3)) * WTILE;

            // Software-pipelined B loads: double-buffered registers, each
            // ldsm issued one full 8-MMA step before its first consumer.
            // step s = ks*4 + h; offB index is [h][ks].
            #define MMA_PAIR(ii)                                                   \
                {                                                                  \
                    unsigned bb0[4], bb1[4];                                       \
                    ldm_x4(w_base + offB[0][0], bb0[0], bb0[1], bb0[2], bb0[3]);   \
                    _Pragma("unroll")                                              \
                    for (int s = 0; s < 16; s++) {                                 \
                        const int ks = s >> 2, h = s & 3;                          \
                        unsigned* bc = (s & 1) ? bb1 : bb0;                        \
                        unsigned* bn = (s & 1) ? bb0 : bb1;                        \
                        if (s < 15) {                                              \
                            const int s2 = s + 1;                                  \
                            ldm_x4(w_base + offB[s2 & 3][s2 >> 2],                 \
                                   bn[0], bn[1], bn[2], bn[3]);                    \
                        }                                                          \
                        mma16816(acc[0][h * 2],     Af[ii][0][ks], bc[0], bc[2]);  \
                        mma16816(acc[0][h * 2 + 1], Af[ii][0][ks], bc[1], bc[3]);  \
                        mma16816(acc[1][h * 2],     Af[ii][1][ks], bc[0], bc[2]);  \
                        mma16816(acc[1][h * 2 + 1], Af[ii][1][ks], bc[1], bc[3]);  \
                    }                                                              \
                }

            if      (i == 0) { MMA_PAIR(0) }
            else if (i == 1) { MMA_PAIR(1) }
            else if (i == 2) { MMA_PAIR(2) }
            else             { MMA_PAIR(3) }
            #undef MMA_PAIR

            // ---- epilogue at end of j: dot rows of acc with x_j ----
            if (jlast) {
                const char* xjp = cross ? (smem + XJOFF)
                                        : (smem + (size_t)j * XTILE);
                #pragma unroll
                for (int mt = 0; mt < 2; mt++) {
                    const int r0 = wi * 32 + mt * 16 + group;
                    float s0 = 0.0f, s1 = 0.0f;
                    #pragma unroll
                    for (int nt = 0; nt < 8; nt++) {
                        const unsigned off =
                            (unsigned)(r0 * 128 + ((nt ^ (r0 & 7)) << 4) + tid4 * 4);
                        // row r0+8 shares the swizzle term ((r0+8)&7 == r0&7)
                        const __half2 x0 = *reinterpret_cast<const __half2*>(xjp + off);
                        const __half2 x1 = *reinterpret_cast<const __half2*>(xjp + off + 1024);
                        float2 f0 = __half22float2(x0);
                        float2 f1 = __half22float2(x1);
                        s0 = fmaf(acc[mt][nt][0], f0.x, s0);
                        s0 = fmaf(acc[mt][nt][1], f0.y, s0);
                        s1 = fmaf(acc[mt][nt][2], f1.x, s1);
                        s1 = fmaf(acc[mt][nt][3], f1.y, s1);
                    }
                    tot[mt][0] += s0;
                    tot[mt][1] += s1;
                }
            }
        }
    }

    // ---- final reduction + writeback (one atomicAdd per row) ----
    #pragma unroll
    for (int mt = 0; mt < 2; mt++)
        #pragma unroll
        for (int h = 0; h < 2; h++) {
            float v = tot[mt][h];
            v += __shfl_xor_sync(0xffffffffu, v, 1);
            v += __shfl_xor_sync(0xffffffffu, v, 2);
            if (tid4 == 0)
                atomicAdd(out + b0 + wi * 32 + mt * 16 + group + h * 8, v);
        }
}

// ---------------- launch ----------------
extern "C" void kernel_launch(void* const* d_in, const int* in_sizes, int n_in,
                              void* d_out, int out_size) {
    const float* x = (const float*)d_in[0];
    const float* W = (const float*)d_in[1];
    float* out = (float*)d_out;

    static bool attr_done = false;
    if (!attr_done) {
        cudaFuncSetAttribute(fmfm11_kernel, cudaFuncAttributeMaxDynamicSharedMemorySize, DYN_SMEM);
        attr_done = true;
    }

    // single fused prepass: x convert + W convert + zero out
    prepass_kernel<<<(B * F * 8) / 256, 256>>>(x, W, out);

    dim3 grid(21, NTILE);   // type fast dim -> mixed CTA lengths per wave
    fmfm11_kernel<<<grid, 128, DYN_SMEM>>>(out);
}